// round 13
// baseline (speedup 1.0000x reference)
#include <cuda_runtime.h>
#include <cuda_bf16.h>
#include <math.h>

#define BDIM 512
#define DDIM 512
#define CDIM 100000
#define SCALE_F 64.0f
#define MARGIN_F 0.35f

#define TILE_N 128
#define NT 782                          // ceil(100000/128)
#define NPART (NT * 4)                  // per-row partials: 2 groups x 2 wn per tile
#define GRIDX 37                        // 37*8 = 296 CTAs = 1 wave @ 2 CTA/SM

#define BM 64
#define ASTRIDE_B 1040                  // A smem row stride (512*2 + 16)
#define BSTRIDE_B 144                   // B smem row stride (64*2 + 16)
#define A_SMEM_BYTES (BM * ASTRIDE_B)               // 66560
#define G_STAGE (64 * BSTRIDE_B)                    // 9216 (64 rows per group)
#define OFF_B A_SMEM_BYTES
#define OFF_RSS (OFF_B + 2 * 2 * G_STAGE)           // 103424
#define SMEM_DYN (OFF_RSS + 2 * 64 * 4)             // 103936  (2 CTAs fit: <114KB)

// ---------------- device scratch ----------------
__device__ __nv_bfloat16 g_xb[BDIM * DDIM];
__device__ float         g_xn[BDIM * DDIM];
__device__ float         g_pm[(size_t)BDIM * NPART];
__device__ float         g_ps[(size_t)BDIM * NPART];
__device__ float         g_cosgt[BDIM];
__device__ float         g_nll[BDIM];
__device__ int           g_is64;

// ---------------- helpers ----------------
__device__ __forceinline__ unsigned smem_u32(const void* p) {
    unsigned a;
    asm("{ .reg .u64 t; cvta.to.shared.u64 t, %1; cvt.u32.u64 %0, t; }" : "=r"(a) : "l"(p));
    return a;
}
#define BAR_G(id) asm volatile("bar.sync %0, 128;" :: "r"(id) : "memory")

__device__ __forceinline__ uint2 cvt_bf16x4(float4 v) {
    __nv_bfloat162 a = __floats2bfloat162_rn(v.x, v.y);
    __nv_bfloat162 b = __floats2bfloat162_rn(v.z, v.w);
    uint2 u; u.x = *(unsigned*)&a; u.y = *(unsigned*)&b; return u;
}

// ---------------- small kernels ----------------
__global__ void detect_gt_kernel(const int* __restrict__ graw) {
    __shared__ int any_nz;
    if (threadIdx.x == 0) any_nz = 0;
    __syncthreads();
    if ((threadIdx.x & 1) && graw[threadIdx.x] != 0) any_nz = 1;
    __syncthreads();
    if (threadIdx.x == 0) g_is64 = any_nz ? 0 : 1;
}

__global__ void __launch_bounds__(128) norm_x_kernel(const float* __restrict__ x) {
    int b = blockIdx.x, tid = threadIdx.x;
    float4 v = ((const float4*)(x + (size_t)b * DDIM))[tid];
    float ss = v.x*v.x + v.y*v.y + v.z*v.z + v.w*v.w;
    #pragma unroll
    for (int o = 16; o; o >>= 1) ss += __shfl_xor_sync(0xffffffffu, ss, o);
    __shared__ float sm[4];
    if ((tid & 31) == 0) sm[tid >> 5] = ss;
    __syncthreads();
    float tot = sm[0] + sm[1] + sm[2] + sm[3];
    float r = 1.0f / fmaxf(sqrtf(tot), 1e-12f);
    float4 n = make_float4(v.x*r, v.y*r, v.z*r, v.w*r);
    ((float4*)(g_xn + (size_t)b * DDIM))[tid] = n;
    __nv_bfloat162* dst = (__nv_bfloat162*)(g_xb + (size_t)b * DDIM);
    dst[tid * 2 + 0] = __floats2bfloat162_rn(n.x, n.y);
    dst[tid * 2 + 1] = __floats2bfloat162_rn(n.z, n.w);
}

__global__ void __launch_bounds__(128) cosgt_kernel(const void* __restrict__ gt,
                                                    const float* __restrict__ wt) {
    int b = blockIdx.x, tid = threadIdx.x;
    long long c = g_is64 ? ((const long long*)gt)[b] : (long long)((const int*)gt)[b];
    float4 w  = ((const float4*)(wt + (size_t)c * DDIM))[tid];
    float4 xn = ((const float4*)(g_xn + (size_t)b * DDIM))[tid];
    float ss = w.x*w.x + w.y*w.y + w.z*w.z + w.w*w.w;
    float dp = w.x*xn.x + w.y*xn.y + w.z*xn.z + w.w*xn.w;
    #pragma unroll
    for (int o = 16; o; o >>= 1) {
        ss += __shfl_xor_sync(0xffffffffu, ss, o);
        dp += __shfl_xor_sync(0xffffffffu, dp, o);
    }
    __shared__ float sms[4], smd[4];
    if ((tid & 31) == 0) { sms[tid >> 5] = ss; smd[tid >> 5] = dp; }
    __syncthreads();
    if (tid == 0) {
        float tss = sms[0] + sms[1] + sms[2] + sms[3];
        float tdp = smd[0] + smd[1] + smd[2] + smd[3];
        g_cosgt[b] = tdp / fmaxf(sqrtf(tss), 1e-12f);
    }
}

// ---------------- GEMM: BM=64, 2 CTAs/SM, 2 indep groups/CTA ----------------
// grid (37, 8), 256 threads, occupancy 2. Group g = warps g*4..g*4+3 owns output
// cols [nt*128 + g*64, +64), its own B stages + named barrier. Warp tile 32x32.
__global__ void __launch_bounds__(256, 2) gemm_softmax_kernel(const float* __restrict__ wt) {
    extern __shared__ char smem[];
    unsigned sbA = smem_u32(smem);

    int tid  = threadIdx.x;
    int lane = tid & 31;
    int warp = tid >> 5;
    int g    = warp >> 2;       // group 0/1
    int gw   = warp & 3;        // warp in group
    int wm   = gw >> 1;         // 0..1 (32-row warp tiles)
    int wn   = gw & 1;          // 0..1 (32-col warp tiles within group's 64)
    int m0 = blockIdx.y * BM;
    int bx = blockIdx.x;
    int barid = g + 1;

    int gtid = tid & 127;
    int seg = gtid & 15;        // float4 segment within 64-fp32 chunk row
    int rb  = gtid >> 4;        // 0..7
    const float4* wsrc = (const float4*)wt;

    unsigned sbBg = sbA + OFF_B + g * (2 * G_STAGE);
    float* sRssG  = (float*)(smem + OFF_RSS) + g * 64;

    // ---- stage A[64x512] bf16 (all 256 threads) ----
    #pragma unroll
    for (int it = 0; it < 16; it++) {
        int idx = it * 256 + tid;
        int r = idx >> 6, s = idx & 63;
        uint4 v = *(const uint4*)(g_xb + (size_t)(m0 + r) * DDIM + s * 8);
        *(uint4*)(smem + r * ASTRIDE_B + s * 16) = v;
    }

    // ---- prologue: chunk 0 of first tile (group rows) ----
    float4 vreg[8];
    #pragma unroll
    for (int q = 0; q < 8; q++) {
        int rg = bx * TILE_N + g * 64 + rb + q * 8;
        vreg[q] = (rg < CDIM) ? wsrc[(size_t)rg * 128 + seg]
                              : make_float4(0.f, 0.f, 0.f, 0.f);
    }
    __syncthreads();   // A visible; groups independent hereafter

    int g4 = lane >> 2, t4 = lane & 3;

    #pragma unroll 1
    for (int nt = bx; nt < NT; nt += GRIDX) {
        float acc[2][4][4];
        #pragma unroll
        for (int i = 0; i < 2; i++)
            #pragma unroll
            for (int j = 0; j < 4; j++)
                #pragma unroll
                for (int e = 0; e < 4; e++) acc[i][j][e] = 0.0f;

        float ssq[8];
        #pragma unroll
        for (int q = 0; q < 8; q++) ssq[q] = 0.0f;

        #pragma unroll 1
        for (int ck = 0; ck < 8; ck++) {
            BAR_G(barid);   // group's stage (ck&1) fully consumed

            unsigned bst = sbBg + (ck & 1) * G_STAGE;
            #pragma unroll
            for (int q = 0; q < 8; q++) {
                float4 v = vreg[q];
                ssq[q] += v.x*v.x + v.y*v.y + v.z*v.z + v.w*v.w;
                int row = rb + q * 8;
                *(uint2*)(smem + (bst - sbA) + row * BSTRIDE_B + seg * 8) = cvt_bf16x4(v);
            }

            if (ck == 7) {
                #pragma unroll
                for (int q = 0; q < 8; q++) {
                    float s = ssq[q];
                    s += __shfl_xor_sync(0xffffffffu, s, 1);
                    s += __shfl_xor_sync(0xffffffffu, s, 2);
                    s += __shfl_xor_sync(0xffffffffu, s, 4);
                    s += __shfl_xor_sync(0xffffffffu, s, 8);
                    if (seg == 0) sRssG[rb + q * 8] = s;
                }
            } else {
                #pragma unroll
                for (int q = 0; q < 8; q++) {
                    int rg = nt * TILE_N + g * 64 + rb + q * 8;
                    vreg[q] = (rg < CDIM) ? wsrc[(size_t)rg * 128 + (ck + 1) * 16 + seg]
                                          : make_float4(0.f, 0.f, 0.f, 0.f);
                }
            }
            BAR_G(barid);   // stage ready (and sRss visible after ck=7)

            // ---- MMA over group stage (ck&1): 4 k16 steps, warp tile 32x32 ----
            unsigned bB = sbBg + (ck & 1) * G_STAGE;
            #pragma unroll
            for (int k16 = 0; k16 < 4; k16++) {
                unsigned a[2][4];
                #pragma unroll
                for (int i = 0; i < 2; i++) {
                    int r   = wm * 32 + i * 16 + (lane & 15);
                    int col = k16 * 16 + ((lane >> 4) << 3);
                    unsigned addr = sbA + r * ASTRIDE_B + col * 2;
                    asm volatile("ldmatrix.sync.aligned.m8n8.x4.shared.b16 {%0,%1,%2,%3}, [%4];"
                                 : "=r"(a[i][0]), "=r"(a[i][1]), "=r"(a[i][2]), "=r"(a[i][3])
                                 : "r"(addr));
                }
                unsigned bfr[4][2];
                #pragma unroll
                for (int j2 = 0; j2 < 2; j2++) {
                    int nrow = wn * 32 + j2 * 16 + (lane & 7) + ((lane >> 4) << 3);
                    int col  = k16 * 16 + (((lane >> 3) & 1) << 3);
                    unsigned addr = bB + nrow * BSTRIDE_B + col * 2;
                    unsigned r0, r1, r2, r3;
                    asm volatile("ldmatrix.sync.aligned.m8n8.x4.shared.b16 {%0,%1,%2,%3}, [%4];"
                                 : "=r"(r0), "=r"(r1), "=r"(r2), "=r"(r3) : "r"(addr));
                    bfr[j2 * 2 + 0][0] = r0; bfr[j2 * 2 + 0][1] = r1;
                    bfr[j2 * 2 + 1][0] = r2; bfr[j2 * 2 + 1][1] = r3;
                }
                #pragma unroll
                for (int i = 0; i < 2; i++)
                    #pragma unroll
                    for (int j = 0; j < 4; j++)
                        asm volatile(
                            "mma.sync.aligned.m16n8k16.row.col.f32.bf16.bf16.f32 "
                            "{%0,%1,%2,%3},{%4,%5,%6,%7},{%8,%9},{%0,%1,%2,%3};"
                            : "+f"(acc[i][j][0]), "+f"(acc[i][j][1]),
                              "+f"(acc[i][j][2]), "+f"(acc[i][j][3])
                            : "r"(a[i][0]), "r"(a[i][1]), "r"(a[i][2]), "r"(a[i][3]),
                              "r"(bfr[j][0]), "r"(bfr[j][1]));
            }
        }

        // prefetch chunk 0 of next tile (overlaps epilogue)
        if (nt + GRIDX < NT) {
            #pragma unroll
            for (int q = 0; q < 8; q++) {
                int rg = (nt + GRIDX) * TILE_N + g * 64 + rb + q * 8;
                vreg[q] = (rg < CDIM) ? wsrc[(size_t)rg * 128 + seg]
                                      : make_float4(0.f, 0.f, 0.f, 0.f);
            }
        }

        // ---- per-warp epilogue: z = acc * SCALE * rsqrt(||w||^2) ----
        int n0 = nt * TILE_N + g * 64;
        float rn[8];
        #pragma unroll
        for (int j = 0; j < 4; j++)
            #pragma unroll
            for (int e2 = 0; e2 < 2; e2++) {
                int tc = wn * 32 + j * 8 + t4 * 2 + e2;
                rn[j * 2 + e2] = rsqrtf(fmaxf(sRssG[tc], 1e-30f)) * SCALE_F;
            }

        #pragma unroll
        for (int i = 0; i < 2; i++) {
            #pragma unroll
            for (int h = 0; h < 2; h++) {
                float m = -INFINITY;
                float z[8];
                #pragma unroll
                for (int j = 0; j < 4; j++) {
                    #pragma unroll
                    for (int e2 = 0; e2 < 2; e2++) {
                        int gc = n0 + wn * 32 + j * 8 + t4 * 2 + e2;
                        float v = rn[j * 2 + e2] * acc[i][j][h * 2 + e2];
                        z[j * 2 + e2] = (gc < CDIM) ? v : -INFINITY;
                        m = fmaxf(m, z[j * 2 + e2]);
                    }
                }
                m = fmaxf(m, __shfl_xor_sync(0xffffffffu, m, 1));
                m = fmaxf(m, __shfl_xor_sync(0xffffffffu, m, 2));
                float s = 0.0f;
                if (m > -1e37f) {
                    #pragma unroll
                    for (int j8 = 0; j8 < 8; j8++) s += __expf(z[j8] - m);
                }
                s += __shfl_xor_sync(0xffffffffu, s, 1);
                s += __shfl_xor_sync(0xffffffffu, s, 2);
                if (t4 == 0) {
                    int r = m0 + wm * 32 + i * 16 + h * 8 + g4;
                    size_t idx = (size_t)r * NPART + nt * 4 + g * 2 + wn;
                    g_pm[idx] = fmaxf(m, -3.0e38f);   // finite sentinel
                    g_ps[idx] = s;
                }
            }
        }
    }
}

// ---------------- logsumexp merge + margin + NLL ----------------
__global__ void __launch_bounds__(256) reduce_kernel() {
    int b = blockIdx.x, tid = threadIdx.x;
    float M = -INFINITY, S = 0.0f;
    for (int i = tid; i < NPART; i += 256) {
        float m = g_pm[(size_t)b * NPART + i];
        float s = g_ps[(size_t)b * NPART + i];
        if (m > M) { S = S * __expf(M - m) + s; M = m; }
        else       { S += s * __expf(m - M); }
    }
    __shared__ float sm[256], ss[256];
    sm[tid] = M; ss[tid] = S;
    __syncthreads();
    for (int o = 128; o; o >>= 1) {
        if (tid < o) {
            float m2 = sm[tid + o], s2 = ss[tid + o];
            float m1 = sm[tid],     s1 = ss[tid];
            float mn = fmaxf(m1, m2);
            sm[tid] = mn;
            ss[tid] = s1 * __expf(m1 - mn) + s2 * __expf(m2 - mn);
        }
        __syncthreads();
    }
    if (tid == 0) {
        float Mf = sm[0], Sf = ss[0];
        float zg = SCALE_F * g_cosgt[b];
        float zm = zg - SCALE_F * MARGIN_F;
        Sf = Sf - expf(zg - Mf) + expf(zm - Mf);
        float lse = Mf + logf(Sf);
        g_nll[b] = lse - zm;
    }
}

__global__ void __launch_bounds__(512) mean_kernel(float* __restrict__ out) {
    __shared__ float sm[512];
    int t = threadIdx.x;
    sm[t] = g_nll[t];
    __syncthreads();
    for (int o = 256; o; o >>= 1) {
        if (t < o) sm[t] += sm[t + o];
        __syncthreads();
    }
    if (t == 0) out[0] = sm[0] * (1.0f / (float)BDIM);
}

// ---------------- launch ----------------
extern "C" void kernel_launch(void* const* d_in, const int* in_sizes, int n_in,
                              void* d_out, int out_size) {
    const float* x  = (const float*)d_in[0];
    const void*  gt = d_in[1];
    const float* wt = (const float*)d_in[2];
    float* out = (float*)d_out;

    static int smem_set = 0;
    if (!smem_set) {
        cudaFuncSetAttribute(gemm_softmax_kernel,
                             cudaFuncAttributeMaxDynamicSharedMemorySize, SMEM_DYN);
        smem_set = 1;
    }

    detect_gt_kernel<<<1, 512>>>((const int*)gt);
    norm_x_kernel<<<BDIM, 128>>>(x);
    cosgt_kernel<<<BDIM, 128>>>(gt, wt);
    gemm_softmax_kernel<<<dim3(GRIDX, 8), 256, SMEM_DYN>>>(wt);
    reduce_kernel<<<BDIM, 256>>>();
    mean_kernel<<<1, 512>>>(out);
}

// round 14
// speedup vs baseline: 1.1047x; 1.1047x over previous
#include <cuda_runtime.h>
#include <cuda_bf16.h>
#include <math.h>

#define BDIM 512
#define DDIM 512
#define CDIM 100000
#define SCALE_F 64.0f
#define MARGIN_F 0.35f

#define TILE_N 128
#define NT 782                          // ceil(100000/128)
#define NPART (NT * 4)                  // per-row partials: 2 groups x 2 wn per tile
#define GRIDX 37                        // 37*4 = 148 CTAs = 1 wave

#define ASTRIDE_B 1040                  // A smem row stride (512*2 + 16)
#define BSTRIDE_B 144                   // B smem row stride (64*2 + 16)
#define A_SMEM_BYTES (128 * ASTRIDE_B)              // 133120
#define G_STAGE (64 * BSTRIDE_B)                    // 9216 (64 rows per group-stage)
#define OFF_B A_SMEM_BYTES
#define OFF_RSS (OFF_B + 2 * 3 * G_STAGE)           // 188416 (3 stages x 2 groups)
#define SMEM_DYN (OFF_RSS + 2 * 2 * 64 * 4)         // 189440 (sRss: 2 grp x 2 par x 64)

// ---------------- device scratch ----------------
__device__ __nv_bfloat16 g_xb[BDIM * DDIM];
__device__ float         g_xn[BDIM * DDIM];
__device__ float         g_pm[(size_t)BDIM * NPART];
__device__ float         g_ps[(size_t)BDIM * NPART];
__device__ float         g_cosgt[BDIM];
__device__ float         g_nll[BDIM];
__device__ int           g_is64;

// ---------------- helpers ----------------
__device__ __forceinline__ unsigned smem_u32(const void* p) {
    unsigned a;
    asm("{ .reg .u64 t; cvta.to.shared.u64 t, %1; cvt.u32.u64 %0, t; }" : "=r"(a) : "l"(p));
    return a;
}
#define BAR_G(id) asm volatile("bar.sync %0, 192;" :: "r"(id) : "memory")

__device__ __forceinline__ unsigned pack_bf16x2(float a, float b) {
    __nv_bfloat162 t = __floats2bfloat162_rn(a, b);
    return *(unsigned*)&t;
}

// ---------------- small kernels ----------------
__global__ void detect_gt_kernel(const int* __restrict__ graw) {
    __shared__ int any_nz;
    if (threadIdx.x == 0) any_nz = 0;
    __syncthreads();
    if ((threadIdx.x & 1) && graw[threadIdx.x] != 0) any_nz = 1;
    __syncthreads();
    if (threadIdx.x == 0) g_is64 = any_nz ? 0 : 1;
}

__global__ void __launch_bounds__(128) norm_x_kernel(const float* __restrict__ x) {
    int b = blockIdx.x, tid = threadIdx.x;
    float4 v = ((const float4*)(x + (size_t)b * DDIM))[tid];
    float ss = v.x*v.x + v.y*v.y + v.z*v.z + v.w*v.w;
    #pragma unroll
    for (int o = 16; o; o >>= 1) ss += __shfl_xor_sync(0xffffffffu, ss, o);
    __shared__ float sm[4];
    if ((tid & 31) == 0) sm[tid >> 5] = ss;
    __syncthreads();
    float tot = sm[0] + sm[1] + sm[2] + sm[3];
    float r = 1.0f / fmaxf(sqrtf(tot), 1e-12f);
    float4 n = make_float4(v.x*r, v.y*r, v.z*r, v.w*r);
    ((float4*)(g_xn + (size_t)b * DDIM))[tid] = n;
    __nv_bfloat162* dst = (__nv_bfloat162*)(g_xb + (size_t)b * DDIM);
    dst[tid * 2 + 0] = __floats2bfloat162_rn(n.x, n.y);
    dst[tid * 2 + 1] = __floats2bfloat162_rn(n.z, n.w);
}

__global__ void __launch_bounds__(128) cosgt_kernel(const void* __restrict__ gt,
                                                    const float* __restrict__ wt) {
    int b = blockIdx.x, tid = threadIdx.x;
    long long c = g_is64 ? ((const long long*)gt)[b] : (long long)((const int*)gt)[b];
    float4 w  = ((const float4*)(wt + (size_t)c * DDIM))[tid];
    float4 xn = ((const float4*)(g_xn + (size_t)b * DDIM))[tid];
    float ss = w.x*w.x + w.y*w.y + w.z*w.z + w.w*w.w;
    float dp = w.x*xn.x + w.y*xn.y + w.z*xn.z + w.w*xn.w;
    #pragma unroll
    for (int o = 16; o; o >>= 1) {
        ss += __shfl_xor_sync(0xffffffffu, ss, o);
        dp += __shfl_xor_sync(0xffffffffu, dp, o);
    }
    __shared__ float sms[4], smd[4];
    if ((tid & 31) == 0) { sms[tid >> 5] = ss; smd[tid >> 5] = dp; }
    __syncthreads();
    if (tid == 0) {
        float tss = sms[0] + sms[1] + sms[2] + sms[3];
        float tdp = smd[0] + smd[1] + smd[2] + smd[3];
        g_cosgt[b] = tdp / fmaxf(sqrtf(tss), 1e-12f);
    }
}

// ---------------- warp-specialized GEMM + fused softmax partials ----------------
// grid (37, 4), 384 threads. Warps 0-7 consumers (2 groups x 4, warp tile 64x32),
// warps 8-11 producers (2 per group). 3-stage B ring, 1 named barrier per chunk.
__global__ void __launch_bounds__(384, 1) gemm_softmax_kernel(const float* __restrict__ wt) {
    extern __shared__ char smem[];
    unsigned sbA = smem_u32(smem);
    float* sRss = (float*)(smem + OFF_RSS);   // [g][parity][64]

    int tid  = threadIdx.x;
    int lane = tid & 31;
    int warp = tid >> 5;
    int m0 = blockIdx.y * 128;
    int bx = blockIdx.x;

    int ntiles = (NT - bx + GRIDX - 1) / GRIDX;
    int NC = ntiles * 8;
    const float4* wsrc = (const float4*)wt;

    // ---- stage A[128x512] bf16 (all 384 threads) ----
    for (int idx = tid; idx < 128 * 64; idx += 384) {
        int r = idx >> 6, s = idx & 63;
        uint4 v = *(const uint4*)(g_xb + (size_t)(m0 + r) * DDIM + s * 8);
        *(uint4*)(smem + r * ASTRIDE_B + s * 16) = v;
    }
    __syncthreads();

    if (warp >= 8) {
        // ================= PRODUCER =================
        int lw = warp - 8;
        int g  = lw >> 1;                 // group 0/1
        int barid = g + 1;
        int ltid = ((lw & 1) << 5) | lane; // 0..63 within group team
        int seg  = ltid & 7;              // 32B (8-float) segment of 64-float row
        int rowb = ltid >> 3;             // 0..7
        unsigned stage0 = sbA + OFF_B + g * (3 * G_STAGE);
        float* sRssG = sRss + g * 128;

        float4 vreg[8][2];
        float ssq[8];
        #pragma unroll
        for (int q = 0; q < 8; q++) ssq[q] = 0.0f;

        // chunk loader into vreg
        auto LOADC = [&](int s) {
            int ts = s >> 3, sck = s & 7;
            int rbase = (bx + ts * GRIDX) * TILE_N + g * 64;
            #pragma unroll
            for (int q = 0; q < 8; q++) {
                int row = rbase + rowb + q * 8;
                if (row < CDIM) {
                    size_t o = (size_t)row * 128 + sck * 16 + seg * 2;
                    vreg[q][0] = wsrc[o];
                    vreg[q][1] = wsrc[o + 1];
                } else {
                    vreg[q][0] = make_float4(0.f, 0.f, 0.f, 0.f);
                    vreg[q][1] = make_float4(0.f, 0.f, 0.f, 0.f);
                }
            }
        };
        // STS chunk s (in vreg) into its stage; ssq bookkeeping
        auto STSC = [&](int s, int sst) {
            int sck = s & 7;
            if (sck == 0) {
                #pragma unroll
                for (int q = 0; q < 8; q++) ssq[q] = 0.0f;
            }
            unsigned base = stage0 + sst * G_STAGE;
            #pragma unroll
            for (int q = 0; q < 8; q++) {
                float4 a = vreg[q][0], b = vreg[q][1];
                ssq[q] += a.x*a.x + a.y*a.y + a.z*a.z + a.w*a.w
                        + b.x*b.x + b.y*b.y + b.z*b.z + b.w*b.w;
                uint4 u;
                u.x = pack_bf16x2(a.x, a.y); u.y = pack_bf16x2(a.z, a.w);
                u.z = pack_bf16x2(b.x, b.y); u.w = pack_bf16x2(b.z, b.w);
                int rl = rowb + q * 8;
                *(uint4*)(smem + (base - sbA) + rl * BSTRIDE_B + seg * 16) = u;
            }
            if (sck == 7) {
                int par = (s >> 3) & 1;
                #pragma unroll
                for (int q = 0; q < 8; q++) {
                    float v = ssq[q];
                    v += __shfl_xor_sync(0xffffffffu, v, 1);
                    v += __shfl_xor_sync(0xffffffffu, v, 2);
                    v += __shfl_xor_sync(0xffffffffu, v, 4);
                    if (seg == 0) sRssG[par * 64 + rowb + q * 8] = v;
                }
            }
        };

        // prologue: chunks 0,1 -> stages 0,1; chunk 2 -> vreg
        LOADC(0); STSC(0, 0);
        LOADC(1); STSC(1, 1);
        LOADC(2);

        int sst = 2;   // stage for next STS = (c+2)%3, starts at 2
        #pragma unroll 1
        for (int c = 0; c < NC; c++) {
            BAR_G(barid);
            int s = c + 2;
            if (s < NC) STSC(s, sst);
            if (++sst == 3) sst = 0;
            int l = c + 3;
            if (l < NC) LOADC(l);
        }
    } else {
        // ================= CONSUMER =================
        int g  = warp >> 2;
        int gw = warp & 3;
        int wm = gw >> 1;        // 0..1
        int wn = gw & 1;         // 0..1
        int barid = g + 1;
        unsigned stage0 = sbA + OFF_B + g * (3 * G_STAGE);
        float* sRssG = sRss + g * 128;
        int g4 = lane >> 2, t4 = lane & 3;

        float acc[4][4][4];
        int st = 0;   // stage of chunk c = c%3
        #pragma unroll 1
        for (int c = 0; c < NC; c++) {
            int ck = c & 7;
            if (ck == 0) {
                #pragma unroll
                for (int i = 0; i < 4; i++)
                    #pragma unroll
                    for (int j = 0; j < 4; j++)
                        #pragma unroll
                        for (int e = 0; e < 4; e++) acc[i][j][e] = 0.0f;
            }
            BAR_G(barid);

            unsigned bB = stage0 + st * G_STAGE;
            if (++st == 3) st = 0;

            #pragma unroll
            for (int k16 = 0; k16 < 4; k16++) {
                unsigned a[4][4];
                #pragma unroll
                for (int i = 0; i < 4; i++) {
                    int r   = wm * 64 + i * 16 + (lane & 15);
                    int col = k16 * 16 + ((lane >> 4) << 3);
                    unsigned addr = sbA + r * ASTRIDE_B + col * 2;
                    asm volatile("ldmatrix.sync.aligned.m8n8.x4.shared.b16 {%0,%1,%2,%3}, [%4];"
                                 : "=r"(a[i][0]), "=r"(a[i][1]), "=r"(a[i][2]), "=r"(a[i][3])
                                 : "r"(addr));
                }
                unsigned bfr[4][2];
                #pragma unroll
                for (int j2 = 0; j2 < 2; j2++) {
                    int nrow = wn * 32 + j2 * 16 + (lane & 7) + ((lane >> 4) << 3);
                    int col  = k16 * 16 + (((lane >> 3) & 1) << 3);
                    unsigned addr = bB + nrow * BSTRIDE_B + col * 2;
                    unsigned r0, r1, r2, r3;
                    asm volatile("ldmatrix.sync.aligned.m8n8.x4.shared.b16 {%0,%1,%2,%3}, [%4];"
                                 : "=r"(r0), "=r"(r1), "=r"(r2), "=r"(r3) : "r"(addr));
                    bfr[j2 * 2 + 0][0] = r0; bfr[j2 * 2 + 0][1] = r1;
                    bfr[j2 * 2 + 1][0] = r2; bfr[j2 * 2 + 1][1] = r3;
                }
                #pragma unroll
                for (int i = 0; i < 4; i++)
                    #pragma unroll
                    for (int j = 0; j < 4; j++)
                        asm volatile(
                            "mma.sync.aligned.m16n8k16.row.col.f32.bf16.bf16.f32 "
                            "{%0,%1,%2,%3},{%4,%5,%6,%7},{%8,%9},{%0,%1,%2,%3};"
                            : "+f"(acc[i][j][0]), "+f"(acc[i][j][1]),
                              "+f"(acc[i][j][2]), "+f"(acc[i][j][3])
                            : "r"(a[i][0]), "r"(a[i][1]), "r"(a[i][2]), "r"(a[i][3]),
                              "r"(bfr[j][0]), "r"(bfr[j][1]));
            }

            if (ck == 7) {
                // ---- per-warp epilogue for tile tp ----
                int tp = c >> 3;
                int nt = bx + tp * GRIDX;
                int n0 = nt * TILE_N + g * 64;
                const float* rss = sRssG + (tp & 1) * 64;
                float rn[8];
                #pragma unroll
                for (int j = 0; j < 4; j++)
                    #pragma unroll
                    for (int e2 = 0; e2 < 2; e2++) {
                        int tc = wn * 32 + j * 8 + t4 * 2 + e2;
                        rn[j * 2 + e2] = rsqrtf(fmaxf(rss[tc], 1e-30f)) * SCALE_F;
                    }
                #pragma unroll
                for (int i = 0; i < 4; i++) {
                    #pragma unroll
                    for (int h = 0; h < 2; h++) {
                        float m = -INFINITY;
                        float z[8];
                        #pragma unroll
                        for (int j = 0; j < 4; j++) {
                            #pragma unroll
                            for (int e2 = 0; e2 < 2; e2++) {
                                int gc = n0 + wn * 32 + j * 8 + t4 * 2 + e2;
                                float v = rn[j * 2 + e2] * acc[i][j][h * 2 + e2];
                                z[j * 2 + e2] = (gc < CDIM) ? v : -INFINITY;
                                m = fmaxf(m, z[j * 2 + e2]);
                            }
                        }
                        m = fmaxf(m, __shfl_xor_sync(0xffffffffu, m, 1));
                        m = fmaxf(m, __shfl_xor_sync(0xffffffffu, m, 2));
                        float s = 0.0f;
                        if (m > -1e37f) {
                            #pragma unroll
                            for (int j8 = 0; j8 < 8; j8++) s += __expf(z[j8] - m);
                        }
                        s += __shfl_xor_sync(0xffffffffu, s, 1);
                        s += __shfl_xor_sync(0xffffffffu, s, 2);
                        if (t4 == 0) {
                            int r = m0 + wm * 64 + i * 16 + h * 8 + g4;
                            size_t idx = (size_t)r * NPART + nt * 4 + g * 2 + wn;
                            g_pm[idx] = fmaxf(m, -3.0e38f);
                            g_ps[idx] = s;
                        }
                    }
                }
            }
        }
    }
}

// ---------------- logsumexp merge + margin + NLL ----------------
__global__ void __launch_bounds__(256) reduce_kernel() {
    int b = blockIdx.x, tid = threadIdx.x;
    float M = -INFINITY, S = 0.0f;
    for (int i = tid; i < NPART; i += 256) {
        float m = g_pm[(size_t)b * NPART + i];
        float s = g_ps[(size_t)b * NPART + i];
        if (m > M) { S = S * __expf(M - m) + s; M = m; }
        else       { S += s * __expf(m - M); }
    }
    __shared__ float sm[256], ss[256];
    sm[tid] = M; ss[tid] = S;
    __syncthreads();
    for (int o = 128; o; o >>= 1) {
        if (tid < o) {
            float m2 = sm[tid + o], s2 = ss[tid + o];
            float m1 = sm[tid],     s1 = ss[tid];
            float mn = fmaxf(m1, m2);
            sm[tid] = mn;
            ss[tid] = s1 * __expf(m1 - mn) + s2 * __expf(m2 - mn);
        }
        __syncthreads();
    }
    if (tid == 0) {
        float Mf = sm[0], Sf = ss[0];
        float zg = SCALE_F * g_cosgt[b];
        float zm = zg - SCALE_F * MARGIN_F;
        Sf = Sf - expf(zg - Mf) + expf(zm - Mf);
        float lse = Mf + logf(Sf);
        g_nll[b] = lse - zm;
    }
}

__global__ void __launch_bounds__(512) mean_kernel(float* __restrict__ out) {
    __shared__ float sm[512];
    int t = threadIdx.x;
    sm[t] = g_nll[t];
    __syncthreads();
    for (int o = 256; o; o >>= 1) {
        if (t < o) sm[t] += sm[t + o];
        __syncthreads();
    }
    if (t == 0) out[0] = sm[0] * (1.0f / (float)BDIM);
}

// ---------------- launch ----------------
extern "C" void kernel_launch(void* const* d_in, const int* in_sizes, int n_in,
                              void* d_out, int out_size) {
    const float* x  = (const float*)d_in[0];
    const void*  gt = d_in[1];
    const float* wt = (const float*)d_in[2];
    float* out = (float*)d_out;

    static int smem_set = 0;
    if (!smem_set) {
        cudaFuncSetAttribute(gemm_softmax_kernel,
                             cudaFuncAttributeMaxDynamicSharedMemorySize, SMEM_DYN);
        smem_set = 1;
    }

    detect_gt_kernel<<<1, 512>>>((const int*)gt);
    norm_x_kernel<<<BDIM, 128>>>(x);
    cosgt_kernel<<<BDIM, 128>>>(gt, wt);
    gemm_softmax_kernel<<<dim3(GRIDX, 4), 384, SMEM_DYN>>>(wt);
    reduce_kernel<<<BDIM, 256>>>();
    mean_kernel<<<1, 512>>>(out);
}

// round 15
// speedup vs baseline: 1.2938x; 1.1712x over previous
#include <cuda_runtime.h>
#include <cuda_bf16.h>
#include <math.h>

#define BDIM 512
#define DDIM 512
#define CDIM 100000
#define SCALE_F 64.0f
#define MARGIN_F 0.35f

#define TILE_N 192                      // 3 groups x 64 cols
#define NT 521                          // ceil(100000/192); 521*192=100032
#define NPART (NT * 6)                  // per-row partials: 3 groups x 2 wn
#define GRIDX 37                        // 37*4 = 148 CTAs = 1 wave

#define ASTRIDE_B 1040                  // A smem row stride (512*2 + 16)
#define BSTRIDE_B 144                   // B smem row stride (64*2 + 16)
#define A_SMEM_BYTES (128 * ASTRIDE_B)              // 133120
#define G_STAGE (64 * BSTRIDE_B)                    // 9216 (64 rows per stage)
#define OFF_B A_SMEM_BYTES
#define OFF_RSS (OFF_B + 3 * 3 * G_STAGE)           // 216064 (3 grp x 3 stages)
#define SMEM_DYN (OFF_RSS + 3 * 2 * 64 * 4)         // 217600 < 227KB limit

// ---------------- device scratch ----------------
__device__ __nv_bfloat16 g_xb[BDIM * DDIM];
__device__ float         g_xn[BDIM * DDIM];
__device__ float         g_pm[(size_t)BDIM * NPART];
__device__ float         g_ps[(size_t)BDIM * NPART];
__device__ float         g_cosgt[BDIM];
__device__ float         g_nll[BDIM];
__device__ int           g_is64;

// ---------------- helpers ----------------
__device__ __forceinline__ unsigned smem_u32(const void* p) {
    unsigned a;
    asm("{ .reg .u64 t; cvta.to.shared.u64 t, %1; cvt.u32.u64 %0, t; }" : "=r"(a) : "l"(p));
    return a;
}
#define BAR_G(id) asm volatile("bar.sync %0, 128;" :: "r"(id) : "memory")

__device__ __forceinline__ unsigned pack_bf16x2(float a, float b) {
    __nv_bfloat162 t = __floats2bfloat162_rn(a, b);
    return *(unsigned*)&t;
}

// ---------------- small kernels ----------------
__global__ void detect_gt_kernel(const int* __restrict__ graw) {
    __shared__ int any_nz;
    if (threadIdx.x == 0) any_nz = 0;
    __syncthreads();
    if ((threadIdx.x & 1) && graw[threadIdx.x] != 0) any_nz = 1;
    __syncthreads();
    if (threadIdx.x == 0) g_is64 = any_nz ? 0 : 1;
}

__global__ void __launch_bounds__(128) norm_x_kernel(const float* __restrict__ x) {
    int b = blockIdx.x, tid = threadIdx.x;
    float4 v = ((const float4*)(x + (size_t)b * DDIM))[tid];
    float ss = v.x*v.x + v.y*v.y + v.z*v.z + v.w*v.w;
    #pragma unroll
    for (int o = 16; o; o >>= 1) ss += __shfl_xor_sync(0xffffffffu, ss, o);
    __shared__ float sm[4];
    if ((tid & 31) == 0) sm[tid >> 5] = ss;
    __syncthreads();
    float tot = sm[0] + sm[1] + sm[2] + sm[3];
    float r = 1.0f / fmaxf(sqrtf(tot), 1e-12f);
    float4 n = make_float4(v.x*r, v.y*r, v.z*r, v.w*r);
    ((float4*)(g_xn + (size_t)b * DDIM))[tid] = n;
    __nv_bfloat162* dst = (__nv_bfloat162*)(g_xb + (size_t)b * DDIM);
    dst[tid * 2 + 0] = __floats2bfloat162_rn(n.x, n.y);
    dst[tid * 2 + 1] = __floats2bfloat162_rn(n.z, n.w);
}

__global__ void __launch_bounds__(128) cosgt_kernel(const void* __restrict__ gt,
                                                    const float* __restrict__ wt) {
    int b = blockIdx.x, tid = threadIdx.x;
    long long c = g_is64 ? ((const long long*)gt)[b] : (long long)((const int*)gt)[b];
    float4 w  = ((const float4*)(wt + (size_t)c * DDIM))[tid];
    float4 xn = ((const float4*)(g_xn + (size_t)b * DDIM))[tid];
    float ss = w.x*w.x + w.y*w.y + w.z*w.z + w.w*w.w;
    float dp = w.x*xn.x + w.y*xn.y + w.z*xn.z + w.w*xn.w;
    #pragma unroll
    for (int o = 16; o; o >>= 1) {
        ss += __shfl_xor_sync(0xffffffffu, ss, o);
        dp += __shfl_xor_sync(0xffffffffu, dp, o);
    }
    __shared__ float sms[4], smd[4];
    if ((tid & 31) == 0) { sms[tid >> 5] = ss; smd[tid >> 5] = dp; }
    __syncthreads();
    if (tid == 0) {
        float tss = sms[0] + sms[1] + sms[2] + sms[3];
        float tdp = smd[0] + smd[1] + smd[2] + smd[3];
        g_cosgt[b] = tdp / fmaxf(sqrtf(tss), 1e-12f);
    }
}

// ---------------- GEMM: 3 independent 4-warp groups, 3-stage rings ----------------
// grid (37, 4), 384 threads. Group g (warps 4g..4g+3, threads 128g..128g+127)
// owns cols [nt*192 + g*64, +64), its own stages + barrier. Warp tile 64x32.
// Every warp is loader+consumer; one bar.sync(128) per chunk.
__global__ void __launch_bounds__(384, 1) gemm_softmax_kernel(const float* __restrict__ wt) {
    extern __shared__ char smem[];
    unsigned sbA = smem_u32(smem);

    int tid  = threadIdx.x;
    int lane = tid & 31;
    int warp = tid >> 5;
    int g    = warp >> 2;       // group 0..2
    int gw   = warp & 3;
    int wm   = gw >> 1;         // 0..1 (64-row warp tiles)
    int wn   = gw & 1;          // 0..1 (32-col warp tiles in group's 64)
    int m0 = blockIdx.y * 128;
    int bx = blockIdx.x;
    int barid = g + 1;

    int gtid = tid & 127;
    int seg  = gtid & 15;       // float4 segment of 64-float chunk row
    int rowb = gtid >> 4;       // 0..7
    const float4* wsrc = (const float4*)wt;

    unsigned bgrp = OFF_B + g * (3 * G_STAGE);      // group stage base (smem offset)
    float* sRssG = (float*)(smem + OFF_RSS) + g * 128;

    int ntiles = (NT - bx + GRIDX - 1) / GRIDX;
    int NC = ntiles * 8;

    // ---- stage A[128x512] bf16 (all 384 threads) ----
    for (int idx = tid; idx < 128 * 64; idx += 384) {
        int r = idx >> 6, s = idx & 63;
        uint4 v = *(const uint4*)(g_xb + (size_t)(m0 + r) * DDIM + s * 8);
        *(uint4*)(smem + r * ASTRIDE_B + s * 16) = v;
    }
    __syncthreads();

    float4 vreg[8];
    float ssq[8];

    auto LOADC = [&](int s) {
        int ts = s >> 3, sck = s & 7;
        int rbase = (bx + ts * GRIDX) * TILE_N + g * 64;
        #pragma unroll
        for (int q = 0; q < 8; q++) {
            int row = rbase + rowb + q * 8;
            row = (row < CDIM) ? row : (CDIM - 1);   // clamp; masked in epilogue
            vreg[q] = wsrc[(size_t)row * 128 + sck * 16 + seg];
        }
    };
    auto STSC = [&](int s, int sst) {
        int sck = s & 7;
        if (sck == 0) {
            #pragma unroll
            for (int q = 0; q < 8; q++) ssq[q] = 0.0f;
        }
        unsigned base = bgrp + sst * G_STAGE;
        #pragma unroll
        for (int q = 0; q < 8; q++) {
            float4 v = vreg[q];
            ssq[q] += v.x*v.x + v.y*v.y + v.z*v.z + v.w*v.w;
            uint2 u;
            u.x = pack_bf16x2(v.x, v.y);
            u.y = pack_bf16x2(v.z, v.w);
            int rl = rowb + q * 8;
            *(uint2*)(smem + base + rl * BSTRIDE_B + seg * 8) = u;
        }
        if (sck == 7) {
            int par = (s >> 3) & 1;
            #pragma unroll
            for (int q = 0; q < 8; q++) {
                float v = ssq[q];
                v += __shfl_xor_sync(0xffffffffu, v, 1);
                v += __shfl_xor_sync(0xffffffffu, v, 2);
                v += __shfl_xor_sync(0xffffffffu, v, 4);
                v += __shfl_xor_sync(0xffffffffu, v, 8);
                if (seg == 0) sRssG[par * 64 + rowb + q * 8] = v;
            }
        }
    };

    // prologue: chunks 0,1 -> stages 0,1; chunk 2 -> vreg
    LOADC(0); STSC(0, 0);
    LOADC(1); STSC(1, 1);
    LOADC(2);

    int g4 = lane >> 2, t4 = lane & 3;
    int aColOff = (lane >> 4) << 3;

    float acc[4][4][4];
    int sst = 2;   // stage for STS of chunk c+2
    int st  = 0;   // stage of chunk c
    #pragma unroll 1
    for (int c = 0; c < NC; c++) {
        int ck = c & 7;
        if (ck == 0) {
            #pragma unroll
            for (int i = 0; i < 4; i++)
                #pragma unroll
                for (int j = 0; j < 4; j++)
                    #pragma unroll
                    for (int e = 0; e < 4; e++) acc[i][j][e] = 0.0f;
        }
        BAR_G(barid);

        { int s = c + 2; if (s < NC) STSC(s, sst); if (++sst == 3) sst = 0; }
        { int l = c + 3; if (l < NC) LOADC(l); }

        // ---- MMA over stage st: 4 k16 steps ----
        unsigned bB = sbA + bgrp + st * G_STAGE;
        if (++st == 3) st = 0;

        #pragma unroll
        for (int k16 = 0; k16 < 4; k16++) {
            unsigned a[4][4];
            #pragma unroll
            for (int i = 0; i < 4; i++) {
                int r   = wm * 64 + i * 16 + (lane & 15);
                int col = ck * 64 + k16 * 16 + aColOff;   // FIXED: chunk K offset
                unsigned addr = sbA + r * ASTRIDE_B + col * 2;
                asm volatile("ldmatrix.sync.aligned.m8n8.x4.shared.b16 {%0,%1,%2,%3}, [%4];"
                             : "=r"(a[i][0]), "=r"(a[i][1]), "=r"(a[i][2]), "=r"(a[i][3])
                             : "r"(addr));
            }
            unsigned bfr[4][2];
            #pragma unroll
            for (int j2 = 0; j2 < 2; j2++) {
                int nrow = wn * 32 + j2 * 16 + (lane & 7) + ((lane >> 4) << 3);
                int col  = k16 * 16 + (((lane >> 3) & 1) << 3);
                unsigned addr = bB + nrow * BSTRIDE_B + col * 2;
                unsigned r0, r1, r2, r3;
                asm volatile("ldmatrix.sync.aligned.m8n8.x4.shared.b16 {%0,%1,%2,%3}, [%4];"
                             : "=r"(r0), "=r"(r1), "=r"(r2), "=r"(r3) : "r"(addr));
                bfr[j2 * 2 + 0][0] = r0; bfr[j2 * 2 + 0][1] = r1;
                bfr[j2 * 2 + 1][0] = r2; bfr[j2 * 2 + 1][1] = r3;
            }
            #pragma unroll
            for (int i = 0; i < 4; i++)
                #pragma unroll
                for (int j = 0; j < 4; j++)
                    asm volatile(
                        "mma.sync.aligned.m16n8k16.row.col.f32.bf16.bf16.f32 "
                        "{%0,%1,%2,%3},{%4,%5,%6,%7},{%8,%9},{%0,%1,%2,%3};"
                        : "+f"(acc[i][j][0]), "+f"(acc[i][j][1]),
                          "+f"(acc[i][j][2]), "+f"(acc[i][j][3])
                        : "r"(a[i][0]), "r"(a[i][1]), "r"(a[i][2]), "r"(a[i][3]),
                          "r"(bfr[j][0]), "r"(bfr[j][1]));
        }

        if (ck == 7) {
            // ---- per-warp epilogue for tile tp ----
            int tp = c >> 3;
            int nt = bx + tp * GRIDX;
            int n0 = nt * TILE_N + g * 64;
            const float* rss = sRssG + (tp & 1) * 64;
            float rn[8];
            #pragma unroll
            for (int j = 0; j < 4; j++)
                #pragma unroll
                for (int e2 = 0; e2 < 2; e2++) {
                    int tc = wn * 32 + j * 8 + t4 * 2 + e2;
                    rn[j * 2 + e2] = rsqrtf(fmaxf(rss[tc], 1e-30f)) * SCALE_F;
                }
            #pragma unroll
            for (int i = 0; i < 4; i++) {
                #pragma unroll
                for (int h = 0; h < 2; h++) {
                    float m = -INFINITY;
                    float z[8];
                    #pragma unroll
                    for (int j = 0; j < 4; j++) {
                        #pragma unroll
                        for (int e2 = 0; e2 < 2; e2++) {
                            int gc = n0 + wn * 32 + j * 8 + t4 * 2 + e2;
                            float v = rn[j * 2 + e2] * acc[i][j][h * 2 + e2];
                            z[j * 2 + e2] = (gc < CDIM) ? v : -INFINITY;
                            m = fmaxf(m, z[j * 2 + e2]);
                        }
                    }
                    m = fmaxf(m, __shfl_xor_sync(0xffffffffu, m, 1));
                    m = fmaxf(m, __shfl_xor_sync(0xffffffffu, m, 2));
                    float s = 0.0f;
                    if (m > -1e37f) {
                        #pragma unroll
                        for (int j8 = 0; j8 < 8; j8++) s += __expf(z[j8] - m);
                    }
                    s += __shfl_xor_sync(0xffffffffu, s, 1);
                    s += __shfl_xor_sync(0xffffffffu, s, 2);
                    if (t4 == 0) {
                        int r = m0 + wm * 64 + i * 16 + h * 8 + g4;
                        size_t idx = (size_t)r * NPART + nt * 6 + g * 2 + wn;
                        g_pm[idx] = fmaxf(m, -3.0e38f);
                        g_ps[idx] = s;
                    }
                }
            }
        }
    }
}

// ---------------- logsumexp merge + margin + NLL ----------------
__global__ void __launch_bounds__(256) reduce_kernel() {
    int b = blockIdx.x, tid = threadIdx.x;
    float M = -INFINITY, S = 0.0f;
    for (int i = tid; i < NPART; i += 256) {
        float m = g_pm[(size_t)b * NPART + i];
        float s = g_ps[(size_t)b * NPART + i];
        if (m > M) { S = S * __expf(M - m) + s; M = m; }
        else       { S += s * __expf(m - M); }
    }
    __shared__ float sm[256], ss[256];
    sm[tid] = M; ss[tid] = S;
    __syncthreads();
    for (int o = 128; o; o >>= 1) {
        if (tid < o) {
            float m2 = sm[tid + o], s2 = ss[tid + o];
            float m1 = sm[tid],     s1 = ss[tid];
            float mn = fmaxf(m1, m2);
            sm[tid] = mn;
            ss[tid] = s1 * __expf(m1 - mn) + s2 * __expf(m2 - mn);
        }
        __syncthreads();
    }
    if (tid == 0) {
        float Mf = sm[0], Sf = ss[0];
        float zg = SCALE_F * g_cosgt[b];
        float zm = zg - SCALE_F * MARGIN_F;
        Sf = Sf - expf(zg - Mf) + expf(zm - Mf);
        float lse = Mf + logf(Sf);
        g_nll[b] = lse - zm;
    }
}

__global__ void __launch_bounds__(512) mean_kernel(float* __restrict__ out) {
    __shared__ float sm[512];
    int t = threadIdx.x;
    sm[t] = g_nll[t];
    __syncthreads();
    for (int o = 256; o; o >>= 1) {
        if (t < o) sm[t] += sm[t + o];
        __syncthreads();
    }
    if (t == 0) out[0] = sm[0] * (1.0f / (float)BDIM);
}

// ---------------- launch ----------------
extern "C" void kernel_launch(void* const* d_in, const int* in_sizes, int n_in,
                              void* d_out, int out_size) {
    const float* x  = (const float*)d_in[0];
    const void*  gt = d_in[1];
    const float* wt = (const float*)d_in[2];
    float* out = (float*)d_out;

    static int smem_set = 0;
    if (!smem_set) {
        cudaFuncSetAttribute(gemm_softmax_kernel,
                             cudaFuncAttributeMaxDynamicSharedMemorySize, SMEM_DYN);
        smem_set = 1;
    }

    detect_gt_kernel<<<1, 512>>>((const int*)gt);
    norm_x_kernel<<<BDIM, 128>>>(x);
    cosgt_kernel<<<BDIM, 128>>>(gt, wt);
    gemm_softmax_kernel<<<dim3(GRIDX, 4), 384, SMEM_DYN>>>(wt);
    reduce_kernel<<<BDIM, 256>>>();
    mean_kernel<<<1, 512>>>(out);
}